// round 1
// baseline (speedup 1.0000x reference)
#include <cuda_runtime.h>
#include <math.h>

#define T_TOK 2048
#define DIM   2048
#define NEXP  8

// ---------------- scratch (device globals: no allocation allowed) ----------
__device__ float g_xs[T_TOK * DIM];   // x * router score (routed-expert input)
__device__ float g_G [T_TOK * DIM];   // gate projection
__device__ float g_U [T_TOK * DIM];   // up projection
__device__ float g_H [T_TOK * DIM];   // silu(G)*U
__device__ int   g_counts[NEXP];
__device__ int   g_cursor[NEXP];
__device__ int   g_off[NEXP + 1];
__device__ int   g_eidx[T_TOK];
__device__ float g_score[T_TOK];
__device__ int   g_perm[T_TOK];
__device__ int   g_tile_e[32];
__device__ int   g_tile_m[32];
__device__ int   g_ntiles;

// ---------------- tiny setup kernels ---------------------------------------
__global__ void init_kernel() {
  int t = threadIdx.x;
  if (t < NEXP) { g_counts[t] = 0; g_cursor[t] = 0; }
}

// one warp per token: logits(8), argmax (first-max tiebreak like jnp.argmax),
// score = sigmoid(max), xs = x*score, histogram of expert counts
__global__ void router_kernel(const float* __restrict__ x,
                              const float* __restrict__ rw) {
  int tok  = (blockIdx.x * blockDim.x + threadIdx.x) >> 5;
  int lane = threadIdx.x & 31;
  if (tok >= T_TOK) return;
  const float* xr = x + (size_t)tok * DIM;
  float acc[NEXP];
#pragma unroll
  for (int e = 0; e < NEXP; e++) acc[e] = 0.f;
  for (int k = lane; k < DIM; k += 32) {
    float xv = xr[k];
    const float4* w4 = reinterpret_cast<const float4*>(rw + (size_t)k * NEXP);
    float4 w0 = w4[0], w1 = w4[1];
    acc[0] = fmaf(xv, w0.x, acc[0]);
    acc[1] = fmaf(xv, w0.y, acc[1]);
    acc[2] = fmaf(xv, w0.z, acc[2]);
    acc[3] = fmaf(xv, w0.w, acc[3]);
    acc[4] = fmaf(xv, w1.x, acc[4]);
    acc[5] = fmaf(xv, w1.y, acc[5]);
    acc[6] = fmaf(xv, w1.z, acc[6]);
    acc[7] = fmaf(xv, w1.w, acc[7]);
  }
#pragma unroll
  for (int o = 16; o > 0; o >>= 1) {
#pragma unroll
    for (int e = 0; e < NEXP; e++)
      acc[e] += __shfl_down_sync(0xffffffffu, acc[e], o);
  }
  float sc = 0.f;
  if (lane == 0) {
    float mx = acc[0]; int im = 0;
#pragma unroll
    for (int e = 1; e < NEXP; e++) if (acc[e] > mx) { mx = acc[e]; im = e; }
    sc = 1.f / (1.f + expf(-mx));
    g_eidx[tok]  = im;
    g_score[tok] = sc;
    atomicAdd(&g_counts[im], 1);
  }
  sc = __shfl_sync(0xffffffffu, sc, 0);
  const float4* x4 = reinterpret_cast<const float4*>(xr);
  float4* o4 = reinterpret_cast<float4*>(g_xs + (size_t)tok * DIM);
  for (int k = lane; k < DIM / 4; k += 32) {
    float4 v = x4[k];
    v.x *= sc; v.y *= sc; v.z *= sc; v.w *= sc;
    o4[k] = v;
  }
}

// exclusive scan of counts + build per-expert m-tile table (<= 16+7 tiles)
__global__ void offsets_kernel() {
  int o = 0, nt = 0;
  for (int e = 0; e < NEXP; e++) {
    g_off[e] = o;
    int c = g_counts[e];
    for (int m = 0; m < c; m += 128) { g_tile_e[nt] = e; g_tile_m[nt] = o + m; nt++; }
    o += c;
  }
  g_off[NEXP] = o;
  g_ntiles = nt;
}

__global__ void scatter_kernel() {
  int t = blockIdx.x * blockDim.x + threadIdx.x;
  if (t >= T_TOK) return;
  int e = g_eidx[t];
  int p = g_off[e] + atomicAdd(&g_cursor[e], 1);
  g_perm[p] = t;
}

__global__ void swiglu_kernel() {
  int i = blockIdx.x * blockDim.x + threadIdx.x;
  if (i >= T_TOK * DIM / 4) return;
  const float4* G4 = reinterpret_cast<const float4*>(g_G);
  const float4* U4 = reinterpret_cast<const float4*>(g_U);
  float4* H4 = reinterpret_cast<float4*>(g_H);
  float4 g = G4[i], u = U4[i], h;
  h.x = g.x / (1.f + expf(-g.x)) * u.x;
  h.y = g.y / (1.f + expf(-g.y)) * u.y;
  h.z = g.z / (1.f + expf(-g.z)) * u.z;
  h.w = g.w / (1.f + expf(-g.w)) * u.w;
  H4[i] = h;
}

// ---------------- GEMM tile core: 128x128x2048, BK=16, 256 thr, 8x8/thread --
// A: [rows, 2048] row-major (optionally row-gathered via perm)
// B: [2048, 2048] row-major (K x N)
// C: [rows, 2048] (optionally row-scattered via perm, optionally +=)
template<int GA, int SC, int ACCF>
__device__ __forceinline__ void gemm_tile(const float* __restrict__ A,
                                          const float* __restrict__ B,
                                          float* __restrict__ C,
                                          int m0, int mEnd, int n0,
                                          const int* __restrict__ perm) {
  __shared__ __align__(16) float As[16][132];  // transposed, +4 pad
  __shared__ __align__(16) float Bs[16][128];
  const int tid = threadIdx.x;
  const int tx = tid & 15;
  const int ty = tid >> 4;

  float acc[8][8];
#pragma unroll
  for (int i = 0; i < 8; i++)
#pragma unroll
    for (int j = 0; j < 8; j++) acc[i][j] = 0.f;

  // A tile: 128 rows x 4 float4 = 512 chunks; 2 per thread
  const int c1  = tid + 256;
  const int ar0 = tid >> 2,      ar1 = c1 >> 2;
  const int ak0 = (tid & 3) * 4, ak1 = (c1 & 3) * 4;
  const int ga0 = m0 + ar0,      ga1 = m0 + ar1;
  const bool v0 = ga0 < mEnd,    v1 = ga1 < mEnd;
  const int row0 = GA ? (v0 ? perm[ga0] : 0) : ga0;
  const int row1 = GA ? (v1 ? perm[ga1] : 0) : ga1;
  const float* ap0 = A + (size_t)row0 * DIM + ak0;
  const float* ap1 = A + (size_t)row1 * DIM + ak1;
  // B tile: 16 rows x 32 float4 = 512 chunks; 2 per thread
  const int bk0 = tid >> 5, bk1 = bk0 + 8;
  const int bn  = (tid & 31) * 4;
  const float* bp0 = B + (size_t)bk0 * DIM + n0 + bn;
  const float* bp1 = B + (size_t)bk1 * DIM + n0 + bn;

  const float4 z4 = make_float4(0.f, 0.f, 0.f, 0.f);
  float4 ra0 = v0 ? *reinterpret_cast<const float4*>(ap0) : z4;
  float4 ra1 = v1 ? *reinterpret_cast<const float4*>(ap1) : z4;
  float4 rb0 = *reinterpret_cast<const float4*>(bp0);
  float4 rb1 = *reinterpret_cast<const float4*>(bp1);

  for (int kt = 0; kt < DIM / 16; kt++) {
    As[ak0 + 0][ar0] = ra0.x;
    As[ak0 + 1][ar0] = ra0.y;
    As[ak0 + 2][ar0] = ra0.z;
    As[ak0 + 3][ar0] = ra0.w;
    As[ak1 + 0][ar1] = ra1.x;
    As[ak1 + 1][ar1] = ra1.y;
    As[ak1 + 2][ar1] = ra1.z;
    As[ak1 + 3][ar1] = ra1.w;
    *reinterpret_cast<float4*>(&Bs[bk0][bn]) = rb0;
    *reinterpret_cast<float4*>(&Bs[bk1][bn]) = rb1;
    __syncthreads();

    if (kt + 1 < DIM / 16) {  // register prefetch of next k-tile
      const int ko = (kt + 1) * 16;
      ra0 = v0 ? *reinterpret_cast<const float4*>(ap0 + ko) : z4;
      ra1 = v1 ? *reinterpret_cast<const float4*>(ap1 + ko) : z4;
      rb0 = *reinterpret_cast<const float4*>(bp0 + (size_t)ko * DIM);
      rb1 = *reinterpret_cast<const float4*>(bp1 + (size_t)ko * DIM);
    }

#pragma unroll
    for (int kk = 0; kk < 16; kk++) {
      float a[8], b[8];
      *reinterpret_cast<float4*>(&a[0]) = *reinterpret_cast<const float4*>(&As[kk][ty * 8]);
      *reinterpret_cast<float4*>(&a[4]) = *reinterpret_cast<const float4*>(&As[kk][ty * 8 + 4]);
      *reinterpret_cast<float4*>(&b[0]) = *reinterpret_cast<const float4*>(&Bs[kk][tx * 8]);
      *reinterpret_cast<float4*>(&b[4]) = *reinterpret_cast<const float4*>(&Bs[kk][tx * 8 + 4]);
#pragma unroll
      for (int i = 0; i < 8; i++)
#pragma unroll
        for (int j = 0; j < 8; j++)
          acc[i][j] = fmaf(a[i], b[j], acc[i][j]);
    }
    __syncthreads();
  }

#pragma unroll
  for (int i = 0; i < 8; i++) {
    int g = m0 + ty * 8 + i;
    if (g >= mEnd) continue;
    int crow = SC ? perm[g] : g;
    float* cp = C + (size_t)crow * DIM + n0 + tx * 8;
#pragma unroll
    for (int j = 0; j < 8; j += 4) {
      float4 v = make_float4(acc[i][j], acc[i][j + 1], acc[i][j + 2], acc[i][j + 3]);
      if (ACCF) {
        float4 o = *reinterpret_cast<const float4*>(cp + j);
        v.x += o.x; v.y += o.y; v.z += o.z; v.w += o.w;
      }
      *reinterpret_cast<float4*>(cp + j) = v;
    }
  }
}

template<int ACCF>
__global__ void __launch_bounds__(256, 2)
gemm_dense_kernel(const float* __restrict__ A, const float* __restrict__ B,
                  float* __restrict__ C) {
  gemm_tile<0, 0, ACCF>(A, B, C, blockIdx.y * 128, T_TOK, blockIdx.x * 128, nullptr);
}

template<int GA, int SC, int ACCF>
__global__ void __launch_bounds__(256, 2)
gemm_grouped_kernel(const float* __restrict__ A, const float* __restrict__ W,
                    float* __restrict__ C) {
  int ti = blockIdx.y;
  if (ti >= g_ntiles) return;
  int e = g_tile_e[ti];
  gemm_tile<GA, SC, ACCF>(A, W + (size_t)e * DIM * DIM, C,
                          g_tile_m[ti], g_off[e + 1], blockIdx.x * 128, g_perm);
}

// ---------------- launch ----------------------------------------------------
extern "C" void kernel_launch(void* const* d_in, const int* in_sizes, int n_in,
                              void* d_out, int out_size) {
  const float* x  = (const float*)d_in[0];  // hidden_states [1024,2,2048] -> [2048,2048]
  const float* rw = (const float*)d_in[1];  // router_w [2048,8]
  const float* gw = (const float*)d_in[2];  // gate_w [8,2048,2048]
  const float* uw = (const float*)d_in[3];  // up_w
  const float* dw = (const float*)d_in[4];  // down_w
  const float* sg = (const float*)d_in[5];  // shared_gate_w [2048,2048]
  const float* su = (const float*)d_in[6];  // shared_up_w
  const float* sd = (const float*)d_in[7];  // shared_down_w
  float* out = (float*)d_out;

  float *pXs, *pG, *pU, *pH;
  cudaGetSymbolAddress((void**)&pXs, g_xs);
  cudaGetSymbolAddress((void**)&pG,  g_G);
  cudaGetSymbolAddress((void**)&pU,  g_U);
  cudaGetSymbolAddress((void**)&pH,  g_H);

  init_kernel<<<1, 32>>>();
  router_kernel<<<T_TOK / 8, 256>>>(x, rw);
  offsets_kernel<<<1, 1>>>();
  scatter_kernel<<<T_TOK / 256, 256>>>();

  const int swi_blocks = (T_TOK * DIM / 4 + 255) / 256;
  dim3 gden(16, 16);
  // shared expert (uses raw x), plain store into d_out
  gemm_dense_kernel<0><<<gden, 256>>>(x, sg, pG);
  gemm_dense_kernel<0><<<gden, 256>>>(x, su, pU);
  swiglu_kernel<<<swi_blocks, 256>>>();
  gemm_dense_kernel<0><<<gden, 256>>>(pH, sd, out);

  // routed experts (use xs = x*score), accumulate into d_out
  dim3 ggrp(16, 24);
  gemm_grouped_kernel<1, 0, 0><<<ggrp, 256>>>(pXs, gw, pG);
  gemm_grouped_kernel<1, 0, 0><<<ggrp, 256>>>(pXs, uw, pU);
  swiglu_kernel<<<swi_blocks, 256>>>();
  gemm_grouped_kernel<0, 1, 1><<<ggrp, 256>>>(pH, dw, out);
}

// round 4
// speedup vs baseline: 1.7958x; 1.7958x over previous
#include <cuda_runtime.h>
#include <math.h>
#include <stdint.h>

#define T_TOK 2048
#define DIM   2048
#define NEXP  8

// ---------------- scratch (device globals) ----------------------------------
__device__ float g_xs[T_TOK * DIM];
__device__ float g_G [T_TOK * DIM];
__device__ float g_U [T_TOK * DIM];
__device__ float g_H [T_TOK * DIM];
__device__ int   g_counts[NEXP];
__device__ int   g_cursor[NEXP];
__device__ int   g_off[NEXP + 1];
__device__ int   g_eidx[T_TOK];
__device__ int   g_perm[T_TOK];
__device__ int   g_tile_e[32];
__device__ int   g_tile_m[32];
__device__ int   g_ntiles;

// ---------------- helpers ----------------------------------------------------
__device__ __forceinline__ uint32_t smem_u32(const void* p) {
  uint32_t a;
  asm("{ .reg .u64 t; cvta.to.shared.u64 t, %1; cvt.u32.u64 %0, t; }" : "=r"(a) : "l"(p));
  return a;
}
__device__ __forceinline__ void cp16(uint32_t dst, const void* src) {
  asm volatile("cp.async.cg.shared.global [%0], [%1], 16;" :: "r"(dst), "l"(src));
}
__device__ __forceinline__ uint32_t pack_hi(float x, float y) {
  return __byte_perm(__float_as_uint(x), __float_as_uint(y), 0x7632);
}
__device__ __forceinline__ uint32_t pack_lo(float x, float y) {
  float lx = x - __uint_as_float(__float_as_uint(x) & 0xFFFF0000u);
  float ly = y - __uint_as_float(__float_as_uint(y) & 0xFFFF0000u);
  uint32_t r;
  asm("cvt.rn.bf16x2.f32 %0, %1, %2;" : "=r"(r) : "f"(ly), "f"(lx));
  return r;
}
__device__ __forceinline__ void mma16816(float* d, const uint32_t* a,
                                         uint32_t b0, uint32_t b1) {
  asm volatile("mma.sync.aligned.m16n8k16.row.col.f32.bf16.bf16.f32 "
               "{%0,%1,%2,%3}, {%4,%5,%6,%7}, {%8,%9}, {%0,%1,%2,%3};"
               : "+f"(d[0]), "+f"(d[1]), "+f"(d[2]), "+f"(d[3])
               : "r"(a[0]), "r"(a[1]), "r"(a[2]), "r"(a[3]), "r"(b0), "r"(b1));
}

// ---------------- tiny setup kernels ----------------------------------------
__global__ void init_kernel() {
  int t = threadIdx.x;
  if (t < NEXP) { g_counts[t] = 0; g_cursor[t] = 0; }
}

__global__ void router_kernel(const float* __restrict__ x,
                              const float* __restrict__ rw) {
  int tok  = (blockIdx.x * blockDim.x + threadIdx.x) >> 5;
  int lane = threadIdx.x & 31;
  if (tok >= T_TOK) return;
  const float* xr = x + (size_t)tok * DIM;
  float acc[NEXP];
#pragma unroll
  for (int e = 0; e < NEXP; e++) acc[e] = 0.f;
  for (int k = lane; k < DIM; k += 32) {
    float xv = xr[k];
    const float4* w4 = reinterpret_cast<const float4*>(rw + (size_t)k * NEXP);
    float4 w0 = w4[0], w1 = w4[1];
    acc[0] = fmaf(xv, w0.x, acc[0]); acc[1] = fmaf(xv, w0.y, acc[1]);
    acc[2] = fmaf(xv, w0.z, acc[2]); acc[3] = fmaf(xv, w0.w, acc[3]);
    acc[4] = fmaf(xv, w1.x, acc[4]); acc[5] = fmaf(xv, w1.y, acc[5]);
    acc[6] = fmaf(xv, w1.z, acc[6]); acc[7] = fmaf(xv, w1.w, acc[7]);
  }
#pragma unroll
  for (int o = 16; o > 0; o >>= 1)
#pragma unroll
    for (int e = 0; e < NEXP; e++)
      acc[e] += __shfl_down_sync(0xffffffffu, acc[e], o);
  float sc = 0.f;
  if (lane == 0) {
    float mx = acc[0]; int im = 0;
#pragma unroll
    for (int e = 1; e < NEXP; e++) if (acc[e] > mx) { mx = acc[e]; im = e; }
    sc = 1.f / (1.f + expf(-mx));
    g_eidx[tok] = im;
    atomicAdd(&g_counts[im], 1);
  }
  sc = __shfl_sync(0xffffffffu, sc, 0);
  const float4* x4 = reinterpret_cast<const float4*>(xr);
  float4* o4 = reinterpret_cast<float4*>(g_xs + (size_t)tok * DIM);
  for (int k = lane; k < DIM / 4; k += 32) {
    float4 v = x4[k];
    v.x *= sc; v.y *= sc; v.z *= sc; v.w *= sc;
    o4[k] = v;
  }
}

__global__ void offsets_kernel() {
  int o = 0, nt = 0;
  for (int e = 0; e < NEXP; e++) {
    g_off[e] = o;
    int c = g_counts[e];
    for (int m = 0; m < c; m += 128) { g_tile_e[nt] = e; g_tile_m[nt] = o + m; nt++; }
    o += c;
  }
  g_off[NEXP] = o;
  g_ntiles = nt;
}

__global__ void scatter_kernel() {
  int t = blockIdx.x * blockDim.x + threadIdx.x;
  if (t >= T_TOK) return;
  int e = g_eidx[t];
  int p = g_off[e] + atomicAdd(&g_cursor[e], 1);
  g_perm[p] = t;
}

__global__ void swiglu_kernel() {
  int i = blockIdx.x * blockDim.x + threadIdx.x;
  if (i >= T_TOK * DIM / 4) return;
  const float4* G4 = reinterpret_cast<const float4*>(g_G);
  const float4* U4 = reinterpret_cast<const float4*>(g_U);
  float4* H4 = reinterpret_cast<float4*>(g_H);
  float4 g = G4[i], u = U4[i], h;
  h.x = g.x / (1.f + expf(-g.x)) * u.x;
  h.y = g.y / (1.f + expf(-g.y)) * u.y;
  h.z = g.z / (1.f + expf(-g.z)) * u.z;
  h.w = g.w / (1.f + expf(-g.w)) * u.w;
  H4[i] = h;
}

// ---------------- HMMA bf16x3 GEMM core --------------------------------------
// C[128,128] tile, K=2048, BK=64 fp32 chunks, 3-stage cp.async pipeline of RAW
// fp32 tiles. fp32 -> bf16 hi/lo split happens at fragment load (registers).
// A smem: [128][72] fp32 (pad 64->72, 16B-aligned rows). B smem: [64][132] fp32.
#define A_STRIDE 72
#define B_STRIDE 132
#define A_STG (128 * A_STRIDE)            // 9216 floats
#define B_STG (64 * B_STRIDE)             // 8448 floats
#define SMEM_F (3 * (A_STG + B_STG))      // 52992 floats = 211968 B
#define NCHUNK (DIM / 64)                 // 32

template<int GA, int SC, int ACCF>
__device__ __forceinline__ void gemm_core(const float* __restrict__ A,
                                          const float* __restrict__ B,
                                          float* __restrict__ C,
                                          int m0, int mEnd, int n0,
                                          const int* __restrict__ perm) {
  extern __shared__ float sm[];
  float* As = sm;
  float* Bs = sm + 3 * A_STG;
  const uint32_t smu = smem_u32(sm);
  const int t = threadIdx.x;
  const int lane = t & 31;
  const int wid  = t >> 5;
  const int wm = wid >> 1;          // 0..3  (m warp, 32 rows)
  const int wn = wid & 1;           // 0..1  (n warp, 64 cols)

  // fill mappings
  const int am  = t >> 1;           // A row 0..127
  const int asg = t & 1;
  const int ga  = m0 + am;
  const bool av = ga < mEnd;
  const int arow = GA ? (av ? perm[ga] : 0) : (av ? ga : 0);
  const float* aRow = A + (size_t)arow * DIM;
  const int bk  = t >> 2;           // B k-row 0..63
  const int bsg = t & 3;
  const float* bRow = B + (size_t)bk * DIM + n0;

  float acc[2][8][4];
#pragma unroll
  for (int i = 0; i < 2; i++)
#pragma unroll
    for (int j = 0; j < 8; j++)
#pragma unroll
      for (int q = 0; q < 4; q++) acc[i][j][q] = 0.f;

  // ---- pipelined fills -----------------------------------------------------
  auto fill = [&](int st, int c) {
    const int k0 = c * 64;
    uint32_t ab = smu + (uint32_t)(st * A_STG + am * A_STRIDE) * 4u;
    const float* ap = aRow + k0;
#pragma unroll
    for (int i = 0; i < 8; i++) {
      int seg = asg + 2 * i;
      cp16(ab + (uint32_t)seg * 16u, ap + seg * 4);
    }
    uint32_t bb = smu + (uint32_t)(3 * A_STG + st * B_STG + bk * B_STRIDE) * 4u;
    const float* bp = bRow + (size_t)k0 * DIM;
#pragma unroll
    for (int i = 0; i < 8; i++) {
      int seg = bsg + 4 * i;
      cp16(bb + (uint32_t)seg * 16u, bp + seg * 4);
    }
  };

  fill(0, 0);
  asm volatile("cp.async.commit_group;" ::: "memory");
  fill(1, 1);
  asm volatile("cp.async.commit_group;" ::: "memory");

  for (int c = 0; c < NCHUNK; c++) {
    asm volatile("cp.async.wait_group 1;" ::: "memory");
    __syncthreads();
    if (c + 2 < NCHUNK) fill((c + 2) % 3, c + 2);
    asm volatile("cp.async.commit_group;" ::: "memory");

    const float* a_s = As + (c % 3) * A_STG;
    const float* b_s = Bs + (c % 3) * B_STG;

#pragma unroll
    for (int ks = 0; ks < 4; ks++) {
      uint32_t ah[2][4], al[2][4];
#pragma unroll
      for (int mt = 0; mt < 2; mt++) {
        const int base = (wm * 32 + mt * 16 + (lane >> 2)) * A_STRIDE +
                         ks * 16 + (lane & 3) * 2;
        float2 p00 = *reinterpret_cast<const float2*>(a_s + base);
        float2 p10 = *reinterpret_cast<const float2*>(a_s + base + 8 * A_STRIDE);
        float2 p01 = *reinterpret_cast<const float2*>(a_s + base + 8);
        float2 p11 = *reinterpret_cast<const float2*>(a_s + base + 8 * A_STRIDE + 8);
        ah[mt][0] = pack_hi(p00.x, p00.y); al[mt][0] = pack_lo(p00.x, p00.y);
        ah[mt][1] = pack_hi(p10.x, p10.y); al[mt][1] = pack_lo(p10.x, p10.y);
        ah[mt][2] = pack_hi(p01.x, p01.y); al[mt][2] = pack_lo(p01.x, p01.y);
        ah[mt][3] = pack_hi(p11.x, p11.y); al[mt][3] = pack_lo(p11.x, p11.y);
      }
#pragma unroll
      for (int nf = 0; nf < 8; nf++) {
        const int nn = wn * 64 + nf * 8 + (lane >> 2);
        const int kk = ks * 16 + (lane & 3) * 2;
        float b00 = b_s[kk * B_STRIDE + nn];
        float b01 = b_s[(kk + 1) * B_STRIDE + nn];
        float b10 = b_s[(kk + 8) * B_STRIDE + nn];
        float b11 = b_s[(kk + 9) * B_STRIDE + nn];
        uint32_t bh0 = pack_hi(b00, b01), bh1 = pack_hi(b10, b11);
        uint32_t bl0 = pack_lo(b00, b01), bl1 = pack_lo(b10, b11);
#pragma unroll
        for (int mt = 0; mt < 2; mt++) {
          mma16816(acc[mt][nf], ah[mt], bh0, bh1);   // hi*hi
          mma16816(acc[mt][nf], ah[mt], bl0, bl1);   // hi*lo
          mma16816(acc[mt][nf], al[mt], bh0, bh1);   // lo*hi
        }
      }
    }
  }

  // ---- epilogue ------------------------------------------------------------
#pragma unroll
  for (int mt = 0; mt < 2; mt++) {
    const int rb = m0 + wm * 32 + mt * 16 + (lane >> 2);
#pragma unroll
    for (int h = 0; h < 2; h++) {
      const int row = rb + h * 8;
      if (row >= mEnd) continue;
      const int crow = SC ? perm[row] : row;
      float* cp = C + (size_t)crow * DIM + n0 + wn * 64 + (lane & 3) * 2;
#pragma unroll
      for (int nf = 0; nf < 8; nf++) {
        float2 v = make_float2(acc[mt][nf][h * 2], acc[mt][nf][h * 2 + 1]);
        float* dst = cp + nf * 8;
        if (ACCF) {
          float2 o = *reinterpret_cast<const float2*>(dst);
          v.x += o.x; v.y += o.y;
        }
        *reinterpret_cast<float2*>(dst) = v;
      }
    }
  }
}

template<int ACCF>
__global__ void __launch_bounds__(256, 1)
gemm_dense_kernel(const float* __restrict__ A, const float* __restrict__ B,
                  float* __restrict__ C) {
  gemm_core<0, 0, ACCF>(A, B, C, blockIdx.y * 128, T_TOK, blockIdx.x * 128, nullptr);
}

template<int GA, int SC, int ACCF>
__global__ void __launch_bounds__(256, 1)
gemm_grouped_kernel(const float* __restrict__ A, const float* __restrict__ W,
                    float* __restrict__ C) {
  int ti = blockIdx.y;
  if (ti >= g_ntiles) return;
  int e = g_tile_e[ti];
  gemm_core<GA, SC, ACCF>(A, W + (size_t)e * DIM * DIM, C,
                          g_tile_m[ti], g_off[e + 1], blockIdx.x * 128, g_perm);
}

// ---------------- launch -----------------------------------------------------
extern "C" void kernel_launch(void* const* d_in, const int* in_sizes, int n_in,
                              void* d_out, int out_size) {
  const float* x  = (const float*)d_in[0];
  const float* rw = (const float*)d_in[1];
  const float* gw = (const float*)d_in[2];
  const float* uw = (const float*)d_in[3];
  const float* dw = (const float*)d_in[4];
  const float* sg = (const float*)d_in[5];
  const float* su = (const float*)d_in[6];
  const float* sd = (const float*)d_in[7];
  float* out = (float*)d_out;

  float *pXs, *pG, *pU, *pH;
  cudaGetSymbolAddress((void**)&pXs, g_xs);
  cudaGetSymbolAddress((void**)&pG,  g_G);
  cudaGetSymbolAddress((void**)&pU,  g_U);
  cudaGetSymbolAddress((void**)&pH,  g_H);

  const int smem_b = SMEM_F * 4;
  cudaFuncSetAttribute(gemm_dense_kernel<0>,
                       cudaFuncAttributeMaxDynamicSharedMemorySize, smem_b);
  cudaFuncSetAttribute(gemm_grouped_kernel<1, 0, 0>,
                       cudaFuncAttributeMaxDynamicSharedMemorySize, smem_b);
  cudaFuncSetAttribute(gemm_grouped_kernel<0, 1, 1>,
                       cudaFuncAttributeMaxDynamicSharedMemorySize, smem_b);

  init_kernel<<<1, 32>>>();
  router_kernel<<<T_TOK / 8, 256>>>(x, rw);
  offsets_kernel<<<1, 1>>>();
  scatter_kernel<<<T_TOK / 256, 256>>>();

  const int swi_blocks = (T_TOK * DIM / 4 + 255) / 256;
  dim3 gden(DIM / 128, T_TOK / 128);   // (16, 16)
  dim3 ggrp(DIM / 128, 24);            // (16, up-to-23 tiles)

  // shared expert
  gemm_dense_kernel<0><<<gden, 256, smem_b>>>(x, sg, pG);
  gemm_dense_kernel<0><<<gden, 256, smem_b>>>(x, su, pU);
  swiglu_kernel<<<swi_blocks, 256>>>();
  gemm_dense_kernel<0><<<gden, 256, smem_b>>>(pH, sd, out);

  // routed experts
  gemm_grouped_kernel<1, 0, 0><<<ggrp, 256, smem_b>>>(pXs, gw, pG);
  gemm_grouped_kernel<1, 0, 0><<<ggrp, 256, smem_b>>>(pXs, uw, pU);
  swiglu_kernel<<<swi_blocks, 256>>>();
  gemm_grouped_kernel<0, 1, 1><<<ggrp, 256, smem_b>>>(pH, dw, out);
}